// round 3
// baseline (speedup 1.0000x reference)
#include <cuda_runtime.h>

#define Bb 2
#define Hh 16
#define Ss 2048
#define Dd 64
#define BHh (Bb*Hh)
#define SCALE 0.125f

// ---------------------------------------------------------------------------
// Mask dtype detection: jax bool may land as int32 (0/1) or uint8 (0/1).
// If int32, bytes at offset%4!=0 are all zero over any prefix; uint8 bool
// data (~50% ones) cannot look like that over 64KB.
// ---------------------------------------------------------------------------
__device__ int g_mask_is_i32;

__global__ void detect_mask_kernel(const unsigned char* __restrict__ M)
{
    __shared__ int nz;
    if (threadIdx.x == 0) nz = 0;
    __syncthreads();
    int local = 0;
    for (int i = threadIdx.x; i < 65536; i += 256)
        if ((i & 3) && M[i]) local++;
    atomicAdd(&nz, local);
    __syncthreads();
    if (threadIdx.x == 0) g_mask_is_i32 = (nz == 0);
}

__device__ __forceinline__ void load_mask4(const unsigned char* __restrict__ M,
                                           size_t idx, int m[4])
{
    if (g_mask_is_i32) {
        int4 v = *(const int4*)((const int*)M + idx);   // idx%4==0 -> 16B aligned
        m[0] = v.x; m[1] = v.y; m[2] = v.z; m[3] = v.w;
    } else {
        uchar4 v = *(const uchar4*)(M + idx);
        m[0] = v.x; m[1] = v.y; m[2] = v.z; m[3] = v.w;
    }
}

// ---------------------------------------------------------------------------
// Kernel A: scores = mask(QK^T * scale) ; softmax rows ; write attention
// CTA: 64 q rows x all 2048 k. K tiled 128 at a time, transposed in smem.
// Thread tile: 8q x 4k (qg = t>>5 owns rows qg*8..+7, kg = t&31 owns cols kg*4..+3)
// A full warp owns the same 8 q rows -> shuffle-only softmax reductions.
// ---------------------------------------------------------------------------
#define A_TQ 64
#define A_TK 128
#define A_QS (A_TQ + 4)
#define A_KS (A_TK + 4)
#define A_SMEM ((Dd*A_QS + Dd*A_KS) * 4)

__global__ __launch_bounds__(256)
void attn_scores_softmax(const float* __restrict__ Q,
                         const float* __restrict__ Kp,
                         const unsigned char* __restrict__ M,
                         float* __restrict__ Att)
{
    extern __shared__ __align__(16) float sm[];
    float* Qt = sm;               // [Dd][A_QS]  (d-major, transposed)
    float* Kt = sm + Dd * A_QS;   // [Dd][A_KS]

    const int t  = threadIdx.x;
    const int bh = blockIdx.y;
    const int b  = bh / Hh;
    const int q0 = blockIdx.x * A_TQ;
    const int qg = t >> 5;
    const int kg = t & 31;

    const float* Qg = Q  + ((size_t)bh * Ss + q0) * Dd;
    const float* Kg = Kp + (size_t)bh * Ss * Dd;
    const unsigned char* Mg = M;                 // indexed in elements
    const size_t mbase = ((size_t)b * Ss + q0) * Ss;
    float* Ag = Att + ((size_t)bh * Ss + q0) * Ss;

    // stage Q transposed & pre-scaled: item (d, q4), gmem reads coalesced in d
    for (int i = t; i < Dd * (A_TQ/4); i += 256) {
        int d  = i & 63;
        int q4 = i >> 6;
        float4 v;
        v.x = Qg[(q4*4+0)*Dd + d] * SCALE;
        v.y = Qg[(q4*4+1)*Dd + d] * SCALE;
        v.z = Qg[(q4*4+2)*Dd + d] * SCALE;
        v.w = Qg[(q4*4+3)*Dd + d] * SCALE;
        *(float4*)&Qt[d*A_QS + q4*4] = v;
    }

    float qmax[8];
    #pragma unroll
    for (int i = 0; i < 8; i++) qmax[i] = -3.402823e38f;

    for (int kt = 0; kt < Ss/A_TK; kt++) {
        const int k0 = kt * A_TK;
        __syncthreads();
        // stage K tile transposed: item (d, k4)
        for (int i = t; i < Dd * (A_TK/4); i += 256) {
            int d  = i & 63;
            int k4 = i >> 6;
            const float* kp = Kg + (size_t)(k0 + k4*4) * Dd + d;
            float4 v;
            v.x = kp[0*Dd]; v.y = kp[1*Dd]; v.z = kp[2*Dd]; v.w = kp[3*Dd];
            *(float4*)&Kt[d*A_KS + k4*4] = v;
        }
        __syncthreads();

        float acc[8][4];
        #pragma unroll
        for (int i = 0; i < 8; i++) {
            acc[i][0] = 0.f; acc[i][1] = 0.f; acc[i][2] = 0.f; acc[i][3] = 0.f;
        }

        #pragma unroll 8
        for (int d = 0; d < Dd; d++) {
            float4 kv = *(const float4*)&Kt[d*A_KS + kg*4];
            float4 a0 = *(const float4*)&Qt[d*A_QS + qg*8];
            float4 a1 = *(const float4*)&Qt[d*A_QS + qg*8 + 4];
            float qv[8] = {a0.x, a0.y, a0.z, a0.w, a1.x, a1.y, a1.z, a1.w};
            #pragma unroll
            for (int i = 0; i < 8; i++) {
                acc[i][0] += qv[i] * kv.x;
                acc[i][1] += qv[i] * kv.y;
                acc[i][2] += qv[i] * kv.z;
                acc[i][3] += qv[i] * kv.w;
            }
        }

        // mask + write raw masked scores + track running max
        #pragma unroll
        for (int i = 0; i < 8; i++) {
            int q = qg*8 + i;
            int mv[4];
            load_mask4(Mg, mbase + (size_t)q*Ss + k0 + kg*4, mv);
            float4 s;
            s.x = mv[0] ? -1.0e9f : acc[i][0];
            s.y = mv[1] ? -1.0e9f : acc[i][1];
            s.z = mv[2] ? -1.0e9f : acc[i][2];
            s.w = mv[3] ? -1.0e9f : acc[i][3];
            qmax[i] = fmaxf(qmax[i], fmaxf(fmaxf(s.x, s.y), fmaxf(s.z, s.w)));
            *(float4*)(Ag + (size_t)q*Ss + k0 + kg*4) = s;
        }
    }

    // per-warp row max (row partials live entirely in one warp)
    float rm[8];
    #pragma unroll
    for (int i = 0; i < 8; i++) {
        float m = qmax[i];
        #pragma unroll
        for (int o = 16; o > 0; o >>= 1)
            m = fmaxf(m, __shfl_xor_sync(0xffffffffu, m, o));
        rm[i] = m;
    }

    // exp + row sum (rereads are this thread's own writes -> no barrier needed)
    float qsum[8];
    #pragma unroll
    for (int i = 0; i < 8; i++) qsum[i] = 0.f;

    for (int kt = 0; kt < Ss/A_TK; kt++) {
        const int k0 = kt * A_TK;
        #pragma unroll
        for (int i = 0; i < 8; i++) {
            int q = qg*8 + i;
            float* p = Ag + (size_t)q*Ss + k0 + kg*4;
            float4 s = *(float4*)p;
            s.x = __expf(s.x - rm[i]);
            s.y = __expf(s.y - rm[i]);
            s.z = __expf(s.z - rm[i]);
            s.w = __expf(s.w - rm[i]);
            qsum[i] += (s.x + s.y) + (s.z + s.w);
            *(float4*)p = s;
        }
    }

    float rs[8];
    #pragma unroll
    for (int i = 0; i < 8; i++) {
        float v = qsum[i];
        #pragma unroll
        for (int o = 16; o > 0; o >>= 1)
            v += __shfl_xor_sync(0xffffffffu, v, o);
        rs[i] = 1.0f / v;
    }

    // normalize
    for (int kt = 0; kt < Ss/A_TK; kt++) {
        const int k0 = kt * A_TK;
        #pragma unroll
        for (int i = 0; i < 8; i++) {
            int q = qg*8 + i;
            float* p = Ag + (size_t)q*Ss + k0 + kg*4;
            float4 s = *(float4*)p;
            s.x *= rs[i]; s.y *= rs[i]; s.z *= rs[i]; s.w *= rs[i];
            *(float4*)p = s;
        }
    }
}

// ---------------------------------------------------------------------------
// Kernel B: context = attention @ V.  CTA: 128 q x 64 d, K tiles of 64.
// Thread tile: 8q x 4d (qg = t>>4, dg = t&15). attention tile transposed.
// ---------------------------------------------------------------------------
#define B_TQ 128
#define B_TK 64
#define B_AS (B_TQ + 4)
#define B_VS (Dd + 4)
#define B_SMEM ((B_TK*B_AS + B_TK*B_VS) * 4)

__global__ __launch_bounds__(256)
void attn_context(const float* __restrict__ Att,
                  const float* __restrict__ V,
                  float* __restrict__ Ctx)
{
    extern __shared__ __align__(16) float sm[];
    float* At = sm;                 // [B_TK][B_AS]  (k-major, transposed)
    float* Vs = sm + B_TK * B_AS;   // [B_TK][B_VS]

    const int t  = threadIdx.x;
    const int bh = blockIdx.y;
    const int q0 = blockIdx.x * B_TQ;
    const int qg = t >> 4;    // 0..15 -> rows qg*8..+7
    const int dg = t & 15;    // cols dg*4..+3

    const float* Ag = Att + ((size_t)bh * Ss + q0) * Ss;
    const float* Vg = V + (size_t)bh * Ss * Dd;
    float* Cg = Ctx + ((size_t)bh * Ss + q0) * Dd;

    float acc[8][4];
    #pragma unroll
    for (int i = 0; i < 8; i++) {
        acc[i][0] = 0.f; acc[i][1] = 0.f; acc[i][2] = 0.f; acc[i][3] = 0.f;
    }

    for (int kt = 0; kt < Ss/B_TK; kt++) {
        const int k0 = kt * B_TK;
        __syncthreads();
        // stage attention tile transposed: item (k, q4)
        for (int i = t; i < B_TK * (B_TQ/4); i += 256) {
            int k  = i & 63;
            int q4 = i >> 6;     // 0..31
            const float* ap = Ag + (size_t)(q4*4) * Ss + k0 + k;
            float4 v;
            v.x = ap[0*Ss]; v.y = ap[1*Ss]; v.z = ap[2*Ss]; v.w = ap[3*Ss];
            *(float4*)&At[k*B_AS + q4*4] = v;
        }
        // stage V tile (natural layout)
        for (int i = t; i < B_TK * (Dd/4); i += 256) {
            int k = i >> 4;
            int d = (i & 15) << 2;
            *(float4*)&Vs[k*B_VS + d] =
                *(const float4*)(Vg + (size_t)(k0 + k) * Dd + d);
        }
        __syncthreads();

        #pragma unroll 8
        for (int k = 0; k < B_TK; k++) {
            float4 v  = *(const float4*)&Vs[k*B_VS + dg*4];
            float4 a0 = *(const float4*)&At[k*B_AS + qg*8];
            float4 a1 = *(const float4*)&At[k*B_AS + qg*8 + 4];
            float av[8] = {a0.x, a0.y, a0.z, a0.w, a1.x, a1.y, a1.z, a1.w};
            #pragma unroll
            for (int i = 0; i < 8; i++) {
                acc[i][0] += av[i] * v.x;
                acc[i][1] += av[i] * v.y;
                acc[i][2] += av[i] * v.z;
                acc[i][3] += av[i] * v.w;
            }
        }
    }

    #pragma unroll
    for (int i = 0; i < 8; i++) {
        int q = qg*8 + i;
        float4 o;
        o.x = acc[i][0]; o.y = acc[i][1]; o.z = acc[i][2]; o.w = acc[i][3];
        *(float4*)(Cg + (size_t)q*Dd + dg*4) = o;
    }
}

// ---------------------------------------------------------------------------
// Kernel C: fused fallback (context only, no attention storage).
// ---------------------------------------------------------------------------
#define C_TQ 64
#define C_TK 64
#define C_ST 68
#define C_SMEM (4 * Dd * C_ST * 4)

__global__ __launch_bounds__(256)
void attn_fused_ctx(const float* __restrict__ Q,
                    const float* __restrict__ Kp,
                    const float* __restrict__ V,
                    const unsigned char* __restrict__ M,
                    float* __restrict__ Ctx)
{
    extern __shared__ __align__(16) float sm[];
    float* Qt = sm;                // [Dd][C_ST] transposed
    float* Kt = sm + 1*Dd*C_ST;    // [Dd][C_ST] transposed
    float* Pt = sm + 2*Dd*C_ST;    // [C_TK][C_ST] transposed probs
    float* Vs = sm + 3*Dd*C_ST;    // [C_TK][C_ST] natural

    const int t  = threadIdx.x;
    const int bh = blockIdx.y;
    const int b  = bh / Hh;
    const int q0 = blockIdx.x * C_TQ;
    const int qg = t >> 4;   // 0..15 -> rows qg*4..+3
    const int kg = t & 15;   // cols kg*4..+3 (k in scores, d in ctx)

    const float* Qg = Q  + ((size_t)bh * Ss + q0) * Dd;
    const float* Kg = Kp + (size_t)bh * Ss * Dd;
    const float* Vg = V  + (size_t)bh * Ss * Dd;
    const size_t mbase = ((size_t)b * Ss + q0) * Ss;

    for (int i = t; i < Dd * (C_TQ/4); i += 256) {
        int d = i & 63; int q4 = i >> 6;
        float4 v;
        v.x = Qg[(q4*4+0)*Dd + d] * SCALE;
        v.y = Qg[(q4*4+1)*Dd + d] * SCALE;
        v.z = Qg[(q4*4+2)*Dd + d] * SCALE;
        v.w = Qg[(q4*4+3)*Dd + d] * SCALE;
        *(float4*)&Qt[d*C_ST + q4*4] = v;
    }

    float qmax[4] = {-3.402823e38f, -3.402823e38f, -3.402823e38f, -3.402823e38f};

    // pass 1: row max
    for (int kt = 0; kt < Ss/C_TK; kt++) {
        const int k0 = kt * C_TK;
        __syncthreads();
        for (int i = t; i < Dd * (C_TK/4); i += 256) {
            int d = i & 63; int k4 = i >> 6;
            const float* kp = Kg + (size_t)(k0 + k4*4) * Dd + d;
            float4 v;
            v.x = kp[0*Dd]; v.y = kp[1*Dd]; v.z = kp[2*Dd]; v.w = kp[3*Dd];
            *(float4*)&Kt[d*C_ST + k4*4] = v;
        }
        __syncthreads();
        float acc[4][4];
        #pragma unroll
        for (int i = 0; i < 4; i++) { acc[i][0]=0.f; acc[i][1]=0.f; acc[i][2]=0.f; acc[i][3]=0.f; }
        #pragma unroll 8
        for (int d = 0; d < Dd; d++) {
            float4 kv = *(const float4*)&Kt[d*C_ST + kg*4];
            float4 qv = *(const float4*)&Qt[d*C_ST + qg*4];
            float q4v[4] = {qv.x, qv.y, qv.z, qv.w};
            #pragma unroll
            for (int i = 0; i < 4; i++) {
                acc[i][0] += q4v[i]*kv.x; acc[i][1] += q4v[i]*kv.y;
                acc[i][2] += q4v[i]*kv.z; acc[i][3] += q4v[i]*kv.w;
            }
        }
        #pragma unroll
        for (int i = 0; i < 4; i++) {
            int mv[4];
            load_mask4(M, mbase + (size_t)(qg*4+i)*Ss + k0 + kg*4, mv);
            float s0 = mv[0] ? -1.0e9f : acc[i][0];
            float s1 = mv[1] ? -1.0e9f : acc[i][1];
            float s2 = mv[2] ? -1.0e9f : acc[i][2];
            float s3 = mv[3] ? -1.0e9f : acc[i][3];
            qmax[i] = fmaxf(qmax[i], fmaxf(fmaxf(s0, s1), fmaxf(s2, s3)));
        }
    }
    float rm[4];
    #pragma unroll
    for (int i = 0; i < 4; i++) {
        float m = qmax[i];
        #pragma unroll
        for (int o = 8; o > 0; o >>= 1)
            m = fmaxf(m, __shfl_xor_sync(0xffffffffu, m, o));
        rm[i] = m;
    }

    // pass 2: exp-probs, sum, P@V
    float qsum[4] = {0.f, 0.f, 0.f, 0.f};
    float cacc[4][4];
    #pragma unroll
    for (int i = 0; i < 4; i++) { cacc[i][0]=0.f; cacc[i][1]=0.f; cacc[i][2]=0.f; cacc[i][3]=0.f; }

    for (int kt = 0; kt < Ss/C_TK; kt++) {
        const int k0 = kt * C_TK;
        __syncthreads();
        for (int i = t; i < Dd * (C_TK/4); i += 256) {
            int d = i & 63; int k4 = i >> 6;
            const float* kp = Kg + (size_t)(k0 + k4*4) * Dd + d;
            float4 v;
            v.x = kp[0*Dd]; v.y = kp[1*Dd]; v.z = kp[2*Dd]; v.w = kp[3*Dd];
            *(float4*)&Kt[d*C_ST + k4*4] = v;
        }
        for (int i = t; i < C_TK * (Dd/4); i += 256) {
            int k = i >> 4;
            int d = (i & 15) << 2;
            *(float4*)&Vs[k*C_ST + d] =
                *(const float4*)(Vg + (size_t)(k0 + k) * Dd + d);
        }
        __syncthreads();
        float acc[4][4];
        #pragma unroll
        for (int i = 0; i < 4; i++) { acc[i][0]=0.f; acc[i][1]=0.f; acc[i][2]=0.f; acc[i][3]=0.f; }
        #pragma unroll 8
        for (int d = 0; d < Dd; d++) {
            float4 kv = *(const float4*)&Kt[d*C_ST + kg*4];
            float4 qv = *(const float4*)&Qt[d*C_ST + qg*4];
            float q4v[4] = {qv.x, qv.y, qv.z, qv.w};
            #pragma unroll
            for (int i = 0; i < 4; i++) {
                acc[i][0] += q4v[i]*kv.x; acc[i][1] += q4v[i]*kv.y;
                acc[i][2] += q4v[i]*kv.z; acc[i][3] += q4v[i]*kv.w;
            }
        }
        #pragma unroll
        for (int i = 0; i < 4; i++) {
            int mv[4];
            load_mask4(M, mbase + (size_t)(qg*4+i)*Ss + k0 + kg*4, mv);
            float p0 = __expf((mv[0] ? -1.0e9f : acc[i][0]) - rm[i]);
            float p1 = __expf((mv[1] ? -1.0e9f : acc[i][1]) - rm[i]);
            float p2 = __expf((mv[2] ? -1.0e9f : acc[i][2]) - rm[i]);
            float p3 = __expf((mv[3] ? -1.0e9f : acc[i][3]) - rm[i]);
            qsum[i] += (p0 + p1) + (p2 + p3);
            Pt[(kg*4+0)*C_ST + qg*4+i] = p0;
            Pt[(kg*4+1)*C_ST + qg*4+i] = p1;
            Pt[(kg*4+2)*C_ST + qg*4+i] = p2;
            Pt[(kg*4+3)*C_ST + qg*4+i] = p3;
        }
        __syncthreads();
        #pragma unroll 8
        for (int k = 0; k < C_TK; k++) {
            float4 a = *(const float4*)&Pt[k*C_ST + qg*4];
            float4 v = *(const float4*)&Vs[k*C_ST + kg*4];
            float a4[4] = {a.x, a.y, a.z, a.w};
            #pragma unroll
            for (int i = 0; i < 4; i++) {
                cacc[i][0] += a4[i]*v.x; cacc[i][1] += a4[i]*v.y;
                cacc[i][2] += a4[i]*v.z; cacc[i][3] += a4[i]*v.w;
            }
        }
    }

    float rinv[4];
    #pragma unroll
    for (int i = 0; i < 4; i++) {
        float v = qsum[i];
        #pragma unroll
        for (int o = 8; o > 0; o >>= 1)
            v += __shfl_xor_sync(0xffffffffu, v, o);
        rinv[i] = 1.0f / v;
    }
    #pragma unroll
    for (int i = 0; i < 4; i++) {
        float4 o;
        o.x = cacc[i][0]*rinv[i]; o.y = cacc[i][1]*rinv[i];
        o.z = cacc[i][2]*rinv[i]; o.w = cacc[i][3]*rinv[i];
        *(float4*)(Ctx + ((size_t)bh*Ss + q0 + qg*4 + i)*Dd + kg*4) = o;
    }
}

// ---------------------------------------------------------------------------
extern "C" void kernel_launch(void* const* d_in, const int* in_sizes, int n_in,
                              void* d_out, int out_size)
{
    const float*         Q = (const float*)d_in[0];
    const float*         K = (const float*)d_in[1];
    const float*         V = (const float*)d_in[2];
    const unsigned char* M = (const unsigned char*)d_in[3];
    float* out = (float*)d_out;

    const int CTX = Bb*Hh*Ss*Dd;        // 4,194,304
    const int ATT = Bb*Hh*Ss*Ss;        // 134,217,728

    cudaFuncSetAttribute(attn_scores_softmax,
                         cudaFuncAttributeMaxDynamicSharedMemorySize, A_SMEM);
    cudaFuncSetAttribute(attn_context,
                         cudaFuncAttributeMaxDynamicSharedMemorySize, B_SMEM);
    cudaFuncSetAttribute(attn_fused_ctx,
                         cudaFuncAttributeMaxDynamicSharedMemorySize, C_SMEM);

    detect_mask_kernel<<<1, 256>>>(M);

    if (out_size >= CTX + ATT) {
        // tuple flattened: context first, then attention
        float* ctx = out;
        float* att = out + CTX;
        attn_scores_softmax<<<dim3(Ss/A_TQ, BHh), 256, A_SMEM>>>(Q, K, M, att);
        attn_context<<<dim3(Ss/B_TQ, BHh), 256, B_SMEM>>>(att, V, ctx);
    } else if (out_size >= ATT) {
        // attention only
        attn_scores_softmax<<<dim3(Ss/A_TQ, BHh), 256, A_SMEM>>>(Q, K, M, out);
    } else {
        // context only: fused path, no attention materialization
        attn_fused_ctx<<<dim3(Ss/C_TQ, BHh), 256, C_SMEM>>>(Q, K, V, M, out);
    }
}